// round 3
// baseline (speedup 1.0000x reference)
#include <cuda_runtime.h>
#include <cstdint>
#include <math.h>

#define BATCH 8
#define SEQQ  1024
#define SEQK  1024
#define DM    512
#define NH    8
#define DH    64

// Intermediates (allocation-free: __device__ globals)
__device__ float g_Qp[BATCH * SEQQ * DM];
__device__ float g_Kp[BATCH * SEQK * DM];
__device__ float g_Vp[BATCH * SEQK * DM];
__device__ float g_O [BATCH * SEQQ * DM];

// ---------------------------------------------------------------------------
// helpers
// ---------------------------------------------------------------------------
__device__ __forceinline__ uint32_t f2tf(float x) {
    uint32_t r;
    asm("cvt.rna.tf32.f32 %0, %1;" : "=r"(r) : "f"(x));
    return r;
}

__device__ __forceinline__ void mma_tf32(float d[4], const uint32_t a[4],
                                         const uint32_t b[2]) {
    asm volatile(
        "mma.sync.aligned.m16n8k8.row.col.f32.tf32.tf32.f32 "
        "{%0,%1,%2,%3}, {%4,%5,%6,%7}, {%8,%9}, {%0,%1,%2,%3};"
        : "+f"(d[0]), "+f"(d[1]), "+f"(d[2]), "+f"(d[3])
        : "r"(a[0]), "r"(a[1]), "r"(a[2]), "r"(a[3]), "r"(b[0]), "r"(b[1]));
}

__device__ __forceinline__ void cpasync16(void* smem, const void* g) {
    uint32_t sa = (uint32_t)__cvta_generic_to_shared(smem);
    asm volatile("cp.async.cg.shared.global [%0], [%1], 16;" ::"r"(sa), "l"(g));
}
__device__ __forceinline__ void cp_commit() {
    asm volatile("cp.async.commit_group;");
}

// ---------------------------------------------------------------------------
// GEMM: C[M x 512] = A[M x 512] @ W^T + bias
// 2xTF32 split: A = ah + al (both tf32), W = wh (tf32).
//   C ~= ah*wh + al*wh   (residual error ~= W tf32 rounding, ~1e-4 rel)
// MODE 0: C = A@W^T + b     MODE 1: C = res + relu(A@W^T + b)
// CTA tile 128x64, BK=32, 256 threads, 8 warps as 4(m) x 2(n), warp tile 32x32.
// smem pitch 36 (== 4 mod 32) -> conflict-free fragment LDS.
// ---------------------------------------------------------------------------
#define GPITCH 36
#define GSTG   (128 * GPITCH + 64 * GPITCH)   // floats per stage = 6912

template <int MODE>
__global__ void __launch_bounds__(256, 2) gemm512(
    const float* __restrict__ A, const float* __restrict__ W,
    const float* __restrict__ bias, const float* __restrict__ res,
    float* __restrict__ C)
{
    extern __shared__ float sm[];
    const int tid = threadIdx.x;
    const int lane = tid & 31;
    const int wid = tid >> 5;
    const int warp_m = wid >> 1;      // 0..3  (32 rows each)
    const int warp_n = wid & 1;       // 0..1  (32 cols each)
    const int m0 = blockIdx.y * 128;
    const int n0 = blockIdx.x * 64;

    float acc[2][4][4] = {};          // [mt][nt][frag]

    // stage loader (cp.async)
    auto load_stage = [&](int t) {
        float* As = sm + (t & 1) * GSTG;
        float* Bs = As + 128 * GPITCH;
        int k0 = t * 32;
        #pragma unroll
        for (int i = 0; i < 4; i++) {
            int idx = tid + i * 256;         // 0..1023
            int r = idx >> 3, c4 = idx & 7;  // 128 rows x 8 float4
            cpasync16(&As[r * GPITCH + c4 * 4],
                      &A[(size_t)(m0 + r) * 512 + k0 + c4 * 4]);
        }
        #pragma unroll
        for (int i = 0; i < 2; i++) {
            int idx = tid + i * 256;         // 0..511
            int r = idx >> 3, c4 = idx & 7;  // 64 rows x 8 float4
            cpasync16(&Bs[r * GPITCH + c4 * 4],
                      &W[(size_t)(n0 + r) * 512 + k0 + c4 * 4]);
        }
        cp_commit();
    };

    load_stage(0);

    for (int t = 0; t < 16; t++) {
        if (t + 1 < 16) {
            load_stage(t + 1);
            asm volatile("cp.async.wait_group 1;");
        } else {
            asm volatile("cp.async.wait_group 0;");
        }
        __syncthreads();

        float* As = sm + (t & 1) * GSTG;
        float* Bs = As + 128 * GPITCH;

        #pragma unroll
        for (int ks = 0; ks < 4; ks++) {
            const int kk = ks * 8;
            uint32_t ah[2][4], al[2][4], bh[4][2];
            #pragma unroll
            for (int mt = 0; mt < 2; mt++) {
                int r = warp_m * 32 + mt * 16 + (lane >> 2);
                const float* p = &As[r * GPITCH + kk + (lane & 3)];
                float x0 = p[0], x1 = p[8 * GPITCH], x2 = p[4], x3 = p[8 * GPITCH + 4];
                ah[mt][0] = f2tf(x0); al[mt][0] = f2tf(x0 - __uint_as_float(ah[mt][0]));
                ah[mt][1] = f2tf(x1); al[mt][1] = f2tf(x1 - __uint_as_float(ah[mt][1]));
                ah[mt][2] = f2tf(x2); al[mt][2] = f2tf(x2 - __uint_as_float(ah[mt][2]));
                ah[mt][3] = f2tf(x3); al[mt][3] = f2tf(x3 - __uint_as_float(ah[mt][3]));
            }
            #pragma unroll
            for (int nt = 0; nt < 4; nt++) {
                int n = warp_n * 32 + nt * 8 + (lane >> 2);
                const float* p = &Bs[n * GPITCH + kk + (lane & 3)];
                bh[nt][0] = f2tf(p[0]);
                bh[nt][1] = f2tf(p[4]);
            }
            #pragma unroll
            for (int mt = 0; mt < 2; mt++)
                #pragma unroll
                for (int nt = 0; nt < 4; nt++) {
                    mma_tf32(acc[mt][nt], al[mt], bh[nt]);
                    mma_tf32(acc[mt][nt], ah[mt], bh[nt]);
                }
        }
        __syncthreads();
    }

    // epilogue
    #pragma unroll
    for (int nt = 0; nt < 4; nt++) {
        int col = n0 + warp_n * 32 + nt * 8 + 2 * (lane & 3);
        float b0 = bias[col], b1 = bias[col + 1];
        #pragma unroll
        for (int mt = 0; mt < 2; mt++) {
            int row = m0 + warp_m * 32 + mt * 16 + (lane >> 2);
            float v00 = acc[mt][nt][0] + b0, v01 = acc[mt][nt][1] + b1;
            float v10 = acc[mt][nt][2] + b0, v11 = acc[mt][nt][3] + b1;
            if (MODE == 1) {
                const float* r0 = &res[(size_t)row * 512 + col];
                const float* r1 = &res[(size_t)(row + 8) * 512 + col];
                v00 = r0[0] + fmaxf(v00, 0.0f);
                v01 = r0[1] + fmaxf(v01, 0.0f);
                v10 = r1[0] + fmaxf(v10, 0.0f);
                v11 = r1[1] + fmaxf(v11, 0.0f);
            }
            *(float2*)&C[(size_t)row * 512 + col]       = make_float2(v00, v01);
            *(float2*)&C[(size_t)(row + 8) * 512 + col] = make_float2(v10, v11);
        }
    }
}

// ---------------------------------------------------------------------------
// Flash attention per (b, h, 64 q-rows), TF32 mma (1x; softmax forgives 2e-4).
// smem: Qs[64][68], Ks[64][68], Vs[64][68], Ss[64][68], stats m/l/corr[64]
// 8 warps as 2(m) x 4(n): S/O warp tiles 32x16.
// ---------------------------------------------------------------------------
#define APITCH 68
#define ATSZ   (64 * APITCH)

__global__ void __launch_bounds__(256) attn_kernel(
    const float* __restrict__ Qp, const float* __restrict__ Kp,
    const float* __restrict__ Vp, float* __restrict__ O)
{
    extern __shared__ float sm[];
    float* Qs = sm;
    float* Ks = sm + ATSZ;
    float* Vs = sm + 2 * ATSZ;
    float* Ss = sm + 3 * ATSZ;
    float* sm_m = sm + 4 * ATSZ;
    float* sm_l = sm_m + 64;
    float* sm_c = sm_l + 64;

    const int tid = threadIdx.x;
    const int lane = tid & 31;
    const int wid = tid >> 5;
    const int warp_m = wid >> 2;   // 0..1 (32 q-rows each)
    const int warp_n = wid & 3;    // 0..3 (16 cols each)

    const int q0 = blockIdx.x * 64;
    const int h = blockIdx.y;
    const int b = blockIdx.z;
    const float scale = 0.044194173824159216f;  // 1/sqrt(512)

    const float* Qbase = Qp + (size_t)b * SEQQ * DM + h * DH;
    const float* Kbase = Kp + (size_t)b * SEQK * DM + h * DH;
    const float* Vbase = Vp + (size_t)b * SEQK * DM + h * DH;

    // load Q tile [64 x 64]
    #pragma unroll
    for (int i = 0; i < 4; i++) {
        int idx = tid + i * 256;          // float4 index
        int r = idx >> 4, c4 = idx & 15;
        cpasync16(&Qs[r * APITCH + c4 * 4],
                  &Qbase[(size_t)(q0 + r) * DM + c4 * 4]);
    }
    cp_commit();

    if (tid < 64) { sm_m[tid] = -1e30f; sm_l[tid] = 0.0f; }

    float oacc[2][2][4] = {};

    for (int kt = 0; kt < SEQK; kt += 64) {
        __syncthreads();   // previous tile's reads done; stats/Q init visible
        #pragma unroll
        for (int i = 0; i < 4; i++) {
            int idx = tid + i * 256;
            int r = idx >> 4, c4 = idx & 15;
            cpasync16(&Ks[r * APITCH + c4 * 4],
                      &Kbase[(size_t)(kt + r) * DM + c4 * 4]);
            cpasync16(&Vs[r * APITCH + c4 * 4],
                      &Vbase[(size_t)(kt + r) * DM + c4 * 4]);
        }
        cp_commit();
        asm volatile("cp.async.wait_group 0;");
        __syncthreads();

        // ---- S = Q @ K^T ----
        float sfr[2][2][4] = {};
        #pragma unroll
        for (int ks = 0; ks < 8; ks++) {
            const int kk = ks * 8;
            uint32_t af[2][4], bf[2][2];
            #pragma unroll
            for (int mt = 0; mt < 2; mt++) {
                int r = warp_m * 32 + mt * 16 + (lane >> 2);
                const float* p = &Qs[r * APITCH + kk + (lane & 3)];
                af[mt][0] = f2tf(p[0]);
                af[mt][1] = f2tf(p[8 * APITCH]);
                af[mt][2] = f2tf(p[4]);
                af[mt][3] = f2tf(p[8 * APITCH + 4]);
            }
            #pragma unroll
            for (int nt = 0; nt < 2; nt++) {
                int n = warp_n * 16 + nt * 8 + (lane >> 2);
                const float* p = &Ks[n * APITCH + kk + (lane & 3)];
                bf[nt][0] = f2tf(p[0]);
                bf[nt][1] = f2tf(p[4]);
            }
            #pragma unroll
            for (int mt = 0; mt < 2; mt++)
                #pragma unroll
                for (int nt = 0; nt < 2; nt++)
                    mma_tf32(sfr[mt][nt], af[mt], bf[nt]);
        }

        // write scaled S to smem
        #pragma unroll
        for (int mt = 0; mt < 2; mt++)
            #pragma unroll
            for (int nt = 0; nt < 2; nt++) {
                int r = warp_m * 32 + mt * 16 + (lane >> 2);
                int c = warp_n * 16 + nt * 8 + 2 * (lane & 3);
                *(float2*)&Ss[r * APITCH + c] =
                    make_float2(sfr[mt][nt][0] * scale, sfr[mt][nt][1] * scale);
                *(float2*)&Ss[(r + 8) * APITCH + c] =
                    make_float2(sfr[mt][nt][2] * scale, sfr[mt][nt][3] * scale);
            }
        __syncthreads();

        // ---- online softmax: 4 lanes per row, 16 cols each ----
        {
            int row = tid >> 2, part = tid & 3;
            float* rp = &Ss[row * APITCH + part * 16];
            float4 v0 = *(float4*)&rp[0],  v1 = *(float4*)&rp[4];
            float4 v2 = *(float4*)&rp[8],  v3 = *(float4*)&rp[12];
            float mx = fmaxf(fmaxf(fmaxf(v0.x, v0.y), fmaxf(v0.z, v0.w)),
                             fmaxf(fmaxf(v1.x, v1.y), fmaxf(v1.z, v1.w)));
            mx = fmaxf(mx, fmaxf(fmaxf(fmaxf(v2.x, v2.y), fmaxf(v2.z, v2.w)),
                                 fmaxf(fmaxf(v3.x, v3.y), fmaxf(v3.z, v3.w))));
            mx = fmaxf(mx, __shfl_xor_sync(0xffffffffu, mx, 1));
            mx = fmaxf(mx, __shfl_xor_sync(0xffffffffu, mx, 2));
            float mold = sm_m[row];
            float mnew = fmaxf(mold, mx);
            v0.x = __expf(v0.x - mnew); v0.y = __expf(v0.y - mnew);
            v0.z = __expf(v0.z - mnew); v0.w = __expf(v0.w - mnew);
            v1.x = __expf(v1.x - mnew); v1.y = __expf(v1.y - mnew);
            v1.z = __expf(v1.z - mnew); v1.w = __expf(v1.w - mnew);
            v2.x = __expf(v2.x - mnew); v2.y = __expf(v2.y - mnew);
            v2.z = __expf(v2.z - mnew); v2.w = __expf(v2.w - mnew);
            v3.x = __expf(v3.x - mnew); v3.y = __expf(v3.y - mnew);
            v3.z = __expf(v3.z - mnew); v3.w = __expf(v3.w - mnew);
            float ls = v0.x + v0.y + v0.z + v0.w + v1.x + v1.y + v1.z + v1.w +
                       v2.x + v2.y + v2.z + v2.w + v3.x + v3.y + v3.z + v3.w;
            ls += __shfl_xor_sync(0xffffffffu, ls, 1);
            ls += __shfl_xor_sync(0xffffffffu, ls, 2);
            *(float4*)&rp[0] = v0;  *(float4*)&rp[4] = v1;
            *(float4*)&rp[8] = v2;  *(float4*)&rp[12] = v3;
            if (part == 0) {
                float corr = __expf(mold - mnew);
                sm_m[row] = mnew;
                sm_l[row] = sm_l[row] * corr + ls;
                sm_c[row] = corr;
            }
        }
        __syncthreads();

        // ---- rescale acc, then acc += P @ V ----
        {
            int r0 = warp_m * 32 + (lane >> 2);
            float c0a = sm_c[r0],      c0b = sm_c[r0 + 8];
            float c1a = sm_c[r0 + 16], c1b = sm_c[r0 + 24];
            #pragma unroll
            for (int nt = 0; nt < 2; nt++) {
                oacc[0][nt][0] *= c0a; oacc[0][nt][1] *= c0a;
                oacc[0][nt][2] *= c0b; oacc[0][nt][3] *= c0b;
                oacc[1][nt][0] *= c1a; oacc[1][nt][1] *= c1a;
                oacc[1][nt][2] *= c1b; oacc[1][nt][3] *= c1b;
            }
        }
        #pragma unroll
        for (int ks = 0; ks < 8; ks++) {
            const int kk = ks * 8;
            uint32_t af[2][4], bf[2][2];
            #pragma unroll
            for (int mt = 0; mt < 2; mt++) {
                int r = warp_m * 32 + mt * 16 + (lane >> 2);
                const float* p = &Ss[r * APITCH + kk + (lane & 3)];
                af[mt][0] = f2tf(p[0]);
                af[mt][1] = f2tf(p[8 * APITCH]);
                af[mt][2] = f2tf(p[4]);
                af[mt][3] = f2tf(p[8 * APITCH + 4]);
            }
            #pragma unroll
            for (int nt = 0; nt < 2; nt++) {
                int n = warp_n * 16 + nt * 8 + (lane >> 2);       // d column
                const float* p = &Vs[(kk + (lane & 3)) * APITCH + n];
                bf[nt][0] = f2tf(p[0]);
                bf[nt][1] = f2tf(p[4 * APITCH]);
            }
            #pragma unroll
            for (int mt = 0; mt < 2; mt++)
                #pragma unroll
                for (int nt = 0; nt < 2; nt++)
                    mma_tf32(oacc[mt][nt], af[mt], bf[nt]);
        }
    }
    __syncthreads();

    // epilogue: O = Qh + ctx / l
    float* Obase = O + (size_t)b * SEQQ * DM + h * DH;
    #pragma unroll
    for (int mt = 0; mt < 2; mt++) {
        int r = warp_m * 32 + mt * 16 + (lane >> 2);
        float inv0 = 1.0f / sm_l[r];
        float inv1 = 1.0f / sm_l[r + 8];
        #pragma unroll
        for (int nt = 0; nt < 2; nt++) {
            int c = warp_n * 16 + nt * 8 + 2 * (lane & 3);
            float q00 = Qs[r * APITCH + c],       q01 = Qs[r * APITCH + c + 1];
            float q10 = Qs[(r + 8) * APITCH + c], q11 = Qs[(r + 8) * APITCH + c + 1];
            *(float2*)&Obase[(size_t)(q0 + r) * DM + c] =
                make_float2(q00 + oacc[mt][nt][0] * inv0,
                            q01 + oacc[mt][nt][1] * inv0);
            *(float2*)&Obase[(size_t)(q0 + r + 8) * DM + c] =
                make_float2(q10 + oacc[mt][nt][2] * inv1,
                            q11 + oacc[mt][nt][3] * inv1);
        }
    }
}

// ---------------------------------------------------------------------------
extern "C" void kernel_launch(void* const* d_in, const int* in_sizes, int n_in,
                              void* d_out, int out_size)
{
    const float* Q  = (const float*)d_in[0];
    const float* K  = (const float*)d_in[1];
    const float* Wq = (const float*)d_in[2];
    const float* bq = (const float*)d_in[3];
    const float* Wk = (const float*)d_in[4];
    const float* bk = (const float*)d_in[5];
    const float* Wv = (const float*)d_in[6];
    const float* bv = (const float*)d_in[7];
    const float* Wo = (const float*)d_in[8];
    const float* bo = (const float*)d_in[9];
    float* out = (float*)d_out;

    float *Qp, *Kp, *Vp, *O;
    cudaGetSymbolAddress((void**)&Qp, g_Qp);
    cudaGetSymbolAddress((void**)&Kp, g_Kp);
    cudaGetSymbolAddress((void**)&Vp, g_Vp);
    cudaGetSymbolAddress((void**)&O,  g_O);

    const int smem_gemm = 2 * GSTG * sizeof(float);              // 55296 B
    const int smem_attn = (4 * ATSZ + 192) * sizeof(float);      // 70400 B
    cudaFuncSetAttribute(gemm512<0>,
                         cudaFuncAttributeMaxDynamicSharedMemorySize, smem_gemm);
    cudaFuncSetAttribute(gemm512<1>,
                         cudaFuncAttributeMaxDynamicSharedMemorySize, smem_gemm);
    cudaFuncSetAttribute(attn_kernel,
                         cudaFuncAttributeMaxDynamicSharedMemorySize, smem_attn);

    dim3 gemm_grid(512 / 64, (BATCH * SEQQ) / 128);   // (8, 64)
    gemm512<0><<<gemm_grid, 256, smem_gemm>>>(Q, Wq, bq, nullptr, Qp);
    gemm512<0><<<gemm_grid, 256, smem_gemm>>>(K, Wk, bk, nullptr, Kp);
    gemm512<0><<<gemm_grid, 256, smem_gemm>>>(K, Wv, bv, nullptr, Vp);

    attn_kernel<<<dim3(SEQQ / 64, NH, BATCH), 256, smem_attn>>>(Qp, Kp, Vp, O);

    gemm512<1><<<gemm_grid, 256, smem_gemm>>>(O, Wo, bo, O, out);
}